// round 16
// baseline (speedup 1.0000x reference)
#include <cuda_runtime.h>
#include <cuda_fp16.h>
#include <cstdint>
#include <math.h>

#define T_STEPS 512
#define BATCH   64
#define IN_DIM  1024
#define HID     1024
#define GATES   4096
#define NCTA    128

// ---------------- static scratch ----------------
__device__ uint32_t g_xfrag[(size_t)T_STEPS * 32768];   // 64 MB: x fp16, mma A-frag layout
__device__ uint32_t g_hfrag[(size_t)T_STEPS * 32768];   // 64 MB: h fp16, mma A-frag layout
__device__ int      g_flags[T_STEPS];

// ---------------- helpers ----------------
__device__ __forceinline__ uint32_t pack2h(__half a, __half b) {
    __half2 t = __halves2half2(a, b);
    return *reinterpret_cast<uint32_t*>(&t);
}
__device__ __forceinline__ void mma16816h(float* c, const uint32_t* a, const uint32_t* b) {
    asm volatile(
        "mma.sync.aligned.m16n8k16.row.col.f32.f16.f16.f32 "
        "{%0,%1,%2,%3}, {%4,%5,%6,%7}, {%8,%9}, {%0,%1,%2,%3};\n"
        : "+f"(c[0]), "+f"(c[1]), "+f"(c[2]), "+f"(c[3])
        : "r"(a[0]), "r"(a[1]), "r"(a[2]), "r"(a[3]), "r"(b[0]), "r"(b[1]));
}
__device__ __forceinline__ void flag_release_add(int* p) {
    asm volatile("red.release.gpu.global.add.s32 [%0], %1;" :: "l"(p), "r"(1) : "memory");
}
__device__ __forceinline__ int flag_acquire_ld(const int* p) {
    int v;
    asm volatile("ld.acquire.gpu.global.s32 %0, [%1];" : "=r"(v) : "l"(p) : "memory");
    return v;
}
#define BAR_SYNC(id, cnt)   asm volatile("bar.sync %0, %1;"   :: "r"(id), "r"(cnt) : "memory")
#define BAR_ARRIVE(id, cnt) asm volatile("bar.arrive %0, %1;" :: "r"(id), "r"(cnt) : "memory")
#define BFULL0  1
#define BEMPTY0 3
#define BREC    5

// =====================================================================
// Converter: x fp32 -> fp16 mma A-fragment layout.
// =====================================================================
__global__ __launch_bounds__(128)
void convert_x_kernel(const float* __restrict__ X)
{
    if (blockIdx.x == 0 && blockIdx.y == 0) {
        #pragma unroll
        for (int i = 0; i < 4; i++) g_flags[threadIdx.x + 128 * i] = 0;
    }
    const int kt = blockIdx.x;
    const int t  = blockIdx.y;
    const int mt = threadIdx.x >> 5;
    const int fl = threadIdx.x & 31;
    const int g  = fl >> 2;
    const int tg = fl & 3;
    const int bb = mt * 16 + g;
    const int k  = kt * 16 + tg * 2;

    const float* xt = X + (size_t)t * BATCH * IN_DIM;
    float2 r00 = *(const float2*)(xt + (size_t)bb * IN_DIM + k);
    float2 r10 = *(const float2*)(xt + (size_t)(bb + 8) * IN_DIM + k);
    float2 r01 = *(const float2*)(xt + (size_t)bb * IN_DIM + k + 8);
    float2 r11 = *(const float2*)(xt + (size_t)(bb + 8) * IN_DIM + k + 8);
    uint4 o;
    o.x = pack2h(__float2half(r00.x), __float2half(r00.y));
    o.y = pack2h(__float2half(r10.x), __float2half(r10.y));
    o.z = pack2h(__float2half(r01.x), __float2half(r01.y));
    o.w = pack2h(__float2half(r11.x), __float2half(r11.y));
    *(uint4*)(g_xfrag + (size_t)t * 32768 + kt * 512 + mt * 128 + fl * 4) = o;
}

// =====================================================================
// Fused persistent LSTM: 512 threads.
//   warps 0-7  : recurrence (mt = w&3, nh = w>>2, full K) — R14-proven
//   warps 8-15 : xw producers, warp = (mh = pw&1: 2 m-tiles with B-frag
//                reuse x2, kq = pw>>1: quarter-K). 2x warps vs R14 for
//                latency hiding; bytes unchanged.
// xw handoff: SMEM ping-pong (2 slots x 4 kq-quarters), consumed at
// top of each rec step.
// =====================================================================
#define WS_PITCH 520      // u32 per W column (520 % 32 == 8 -> conflict-free)
#define XWB_STRIDE 36     // floats per row
#define XWB_SIZE  (64 * XWB_STRIDE)

__global__ __launch_bounds__(512, 1)
void lstm_fused_kernel(const float* __restrict__ Wx,
                       const float* __restrict__ Wh,
                       const float* __restrict__ b,
                       float* __restrict__ out,
                       int write_tail)
{
    extern __shared__ char smraw[];
    uint32_t* Whs  = (uint32_t*)smraw;                  // 66560 B
    uint32_t* Wxs  = Whs + 32 * WS_PITCH;               // 66560 B
    float*    xwb  = (float*)(Wxs + 32 * WS_PITCH);     // 8 * 9216 B = 73728 B

    const int tid  = threadIdx.x;
    const int lane = tid & 31;
    const int warp = tid >> 5;
    const int g    = lane >> 2;
    const int tg   = lane & 3;
    const int j0   = blockIdx.x * 8;

    // ---- one-time: Wh & Wx slices -> SMEM fragment layout (reordered cols:
    // c: nh=c>>4, q=(c>>3)&1, cc=c&7; gate=2q+(cc&1), jj=nh*4+(cc>>1)) ----
    for (int i = tid; i < 32 * 1024; i += 512) {
        int c = i & 31;
        int k = i >> 5;
        int nhc = c >> 4, qc = (c >> 3) & 1, cc = c & 7;
        int gate = 2 * qc + (cc & 1);
        int jj   = nhc * 4 + (cc >> 1);
        size_t src = (size_t)k * GATES + gate * HID + j0 + jj;
        int kt = k >> 4, t4 = (k >> 1) & 3, w = (k >> 3) & 1, hf = k & 1;
        int word = c * WS_PITCH + kt * 8 + t4 * 2 + w;
        ((__half*)Whs)[word * 2 + hf] = __float2half(Wh[src]);
        ((__half*)Wxs)[word * 2 + hf] = __float2half(Wx[src]);
    }
    __syncthreads();

    if (warp < 8) {
        // ================== RECURRENCE WARPS ==================
        const int mt = warp & 3;
        const int nh = warp >> 2;
        const int wm = mt * 16;
        const int r0 = wm + g;
        const int r1 = wm + g + 8;
        const int j  = j0 + nh * 4 + tg;
        const int cc4 = (nh * 4 + tg) * 4;

        float breg[4] = { b[j], b[HID + j], b[2 * HID + j], b[3 * HID + j] };
        float creg[2] = {0.f, 0.f};

        for (int t = 0; t < T_STEPS; t++) {
            // ---- consume xw[t] at top of step (4 kq partials) ----
            BAR_SYNC(BFULL0 + (t & 1), 512);
            const float* xb = xwb + (t & 1) * 4 * XWB_SIZE;
            float4 x0 = make_float4(breg[0], breg[1], breg[2], breg[3]);
            float4 x1 = x0;
            #pragma unroll
            for (int q = 0; q < 4; q++) {
                float4 p0 = *(const float4*)(xb + q * XWB_SIZE + r0 * XWB_STRIDE + cc4);
                float4 p1 = *(const float4*)(xb + q * XWB_SIZE + r1 * XWB_STRIDE + cc4);
                x0.x += p0.x; x0.y += p0.y; x0.z += p0.z; x0.w += p0.w;
                x1.x += p1.x; x1.y += p1.y; x1.z += p1.z; x1.w += p1.w;
            }
            BAR_ARRIVE(BEMPTY0 + (t & 1), 512);

            float acc[2][2][4];
            #pragma unroll
            for (int pp = 0; pp < 2; pp++)
                #pragma unroll
                for (int q = 0; q < 2; q++)
                    #pragma unroll
                    for (int c2 = 0; c2 < 4; c2++) acc[pp][q][c2] = 0.f;

            if (t > 0) {
                if (lane == 0) {
                    while (flag_acquire_ld(g_flags + (t - 1)) != NCTA) { }
                }
                __syncwarp();

                const uint32_t* ab = g_hfrag + (size_t)(t - 1) * 32768
                                     + mt * 128 + lane * 4;
                uint4 H[8];
                #pragma unroll
                for (int q = 0; q < 8; q++) H[q] = *(const uint4*)(ab + q * 512);

                #pragma unroll 8
                for (int kt = 0; kt < 64; kt++) {
                    int s = kt & 7;
                    uint32_t ah[4] = {H[s].x, H[s].y, H[s].z, H[s].w};
                    float* a0 = acc[kt & 1][0];
                    float* a1 = acc[kt & 1][1];
                    {
                        int c = nh * 16 + g;
                        uint2 bf = *(const uint2*)(Whs + c * WS_PITCH + kt * 8 + tg * 2);
                        uint32_t bh[2] = {bf.x, bf.y};
                        mma16816h(a0, ah, bh);
                    }
                    {
                        int c = nh * 16 + 8 + g;
                        uint2 bf = *(const uint2*)(Whs + c * WS_PITCH + kt * 8 + tg * 2);
                        uint32_t bh[2] = {bf.x, bf.y};
                        mma16816h(a1, ah, bh);
                    }
                    if (kt + 8 < 64) H[s] = *(const uint4*)(ab + (kt + 8) * 512);
                }
            }

            // ---- in-register activations ----
            float hn[2], cn[2];
            #pragma unroll
            for (int rr = 0; rr < 2; rr++) {
                float xi = rr ? x1.x : x0.x;
                float xf = rr ? x1.y : x0.y;
                float xG = rr ? x1.z : x0.z;
                float xo = rr ? x1.w : x0.w;
                float gi = acc[0][0][2 * rr + 0] + acc[1][0][2 * rr + 0] + xi;
                float gf = acc[0][0][2 * rr + 1] + acc[1][0][2 * rr + 1] + xf;
                float gg = acc[0][1][2 * rr + 0] + acc[1][1][2 * rr + 0] + xG;
                float go = acc[0][1][2 * rr + 1] + acc[1][1][2 * rr + 1] + xo;
                float iv = 1.f / (1.f + expf(-gi));
                float fv = 1.f / (1.f + expf(-gf));
                float gv = tanhf(gg);
                float ov = 1.f / (1.f + expf(-go));
                float c_ = fv * creg[rr] + iv * gv;
                float h_ = ov * tanhf(c_);
                creg[rr] = c_;
                cn[rr] = c_; hn[rr] = h_;
            }

            // ---- publish h fragments ----
            {
                uint32_t packed = pack2h(__float2half(hn[0]), __float2half(hn[1]));
                uint32_t nb = __shfl_xor_sync(0xffffffffu, packed, 1);
                if ((tg & 1) == 0) {
                    uint32_t f0 = (packed & 0xffffu) | (nb << 16);       // row r0
                    uint32_t f1 = (packed >> 16) | (nb & 0xffff0000u);   // row r1
                    int kk = j & 15, kt = j >> 4;
                    int fl = g * 4 + ((kk >> 1) & 3);
                    int rg0 = (kk >> 3) << 1;
                    size_t fb = (size_t)t * 32768 + (size_t)kt * 512 + mt * 128 + fl * 4 + rg0;
                    *(uint2*)(g_hfrag + fb) = make_uint2(f0, f1);
                }
            }

            BAR_SYNC(BREC, 256);
            if (tid == 0) flag_release_add(g_flags + t);

            // ---- off-critical-path output stores ----
            float* hdst = out + (size_t)t * BATCH * HID;
            hdst[(size_t)r0 * HID + j] = hn[0];
            hdst[(size_t)r1 * HID + j] = hn[1];
            if (t == T_STEPS - 1 && write_tail) {
                size_t base = (size_t)T_STEPS * BATCH * HID;
                out[base + (size_t)r0 * HID + j] = hn[0];
                out[base + (size_t)r1 * HID + j] = hn[1];
                out[base + BATCH * HID + (size_t)r0 * HID + j] = cn[0];
                out[base + BATCH * HID + (size_t)r1 * HID + j] = cn[1];
            }
        }
    } else {
        // ================== XW PRODUCER WARPS (8) ==================
        // warp = (mh: m-tiles {2mh, 2mh+1}, kq: quarter-K); all 32 cols.
        const int pw = warp - 8;
        const int mh = pw & 1;
        const int kq = pw >> 1;          // kt2 in [kq*16, kq*16+16)

        for (int t = 0; t < T_STEPS; t++) {
            if (t >= 2) BAR_SYNC(BEMPTY0 + (t & 1), 512);

            const uint32_t* abA = g_xfrag + (size_t)t * 32768
                                  + (size_t)(kq * 16) * 512 + (2 * mh) * 128 + lane * 4;
            const uint32_t* abB = abA + 128;   // m-tile 2mh+1

            uint4 HA[4], HB[4];
            #pragma unroll
            for (int q = 0; q < 4; q++) {
                HA[q] = *(const uint4*)(abA + q * 512);
                HB[q] = *(const uint4*)(abB + q * 512);
            }

            float acc[2][4][4];
            #pragma unroll
            for (int m2 = 0; m2 < 2; m2++)
                #pragma unroll
                for (int q = 0; q < 4; q++)
                    #pragma unroll
                    for (int c2 = 0; c2 < 4; c2++) acc[m2][q][c2] = 0.f;

            #pragma unroll 4
            for (int kt2 = 0; kt2 < 16; kt2++) {
                int s = kt2 & 3;
                int ktg = kq * 16 + kt2;
                uint32_t ahA[4] = {HA[s].x, HA[s].y, HA[s].z, HA[s].w};
                uint32_t ahB[4] = {HB[s].x, HB[s].y, HB[s].z, HB[s].w};
                #pragma unroll
                for (int ct = 0; ct < 4; ct++) {
                    uint2 bf = *(const uint2*)(Wxs + (ct * 8 + g) * WS_PITCH + ktg * 8 + tg * 2);
                    uint32_t bh[2] = {bf.x, bf.y};
                    mma16816h(acc[0][ct], ahA, bh);   // B reused for both m-tiles
                    mma16816h(acc[1][ct], ahB, bh);
                }
                if (kt2 + 4 < 16) {
                    HA[s] = *(const uint4*)(abA + (kt2 + 4) * 512);
                    HB[s] = *(const uint4*)(abB + (kt2 + 4) * 512);
                }
            }

            // write raw partials into kq-quarter of slot (t&1)
            float* xb = xwb + ((t & 1) * 4 + kq) * XWB_SIZE;
            #pragma unroll
            for (int m2 = 0; m2 < 2; m2++) {
                int rb = mh * 32 + m2 * 16 + g;
                #pragma unroll
                for (int nh2 = 0; nh2 < 2; nh2++) {
                    int col4 = (nh2 * 4 + tg) * 4;
                    float4 v0 = make_float4(acc[m2][nh2 * 2][0], acc[m2][nh2 * 2][1],
                                            acc[m2][nh2 * 2 + 1][0], acc[m2][nh2 * 2 + 1][1]);
                    float4 v1 = make_float4(acc[m2][nh2 * 2][2], acc[m2][nh2 * 2][3],
                                            acc[m2][nh2 * 2 + 1][2], acc[m2][nh2 * 2 + 1][3]);
                    *(float4*)(xb + rb * XWB_STRIDE + col4)       = v0;
                    *(float4*)(xb + (rb + 8) * XWB_STRIDE + col4) = v1;
                }
            }
            BAR_ARRIVE(BFULL0 + (t & 1), 512);
        }
    }
}

// =====================================================================
extern "C" void kernel_launch(void* const* d_in, const int* in_sizes, int n_in,
                              void* d_out, int out_size)
{
    const float* x  = (const float*)d_in[0];   // [512,64,1024]
    const float* Wx = (const float*)d_in[1];   // [1024,4096]
    const float* Wh = (const float*)d_in[2];   // [1024,4096]
    const float* b  = (const float*)d_in[3];   // [4096]
    float* out = (float*)d_out;

    convert_x_kernel<<<dim3(64, T_STEPS), 128>>>(x);

    const int smemB = 2 * (32 * WS_PITCH * 4) + 8 * XWB_SIZE * 4;  // 133120 + 73728
    cudaFuncSetAttribute(lstm_fused_kernel,
                         cudaFuncAttributeMaxDynamicSharedMemorySize, smemB);
    int write_tail = (out_size > T_STEPS * BATCH * HID) ? 1 : 0;
    lstm_fused_kernel<<<NCTA, 512, smemB>>>(Wx, Wh, b, out, write_tail);
}

// round 17
// speedup vs baseline: 1.0291x; 1.0291x over previous
#include <cuda_runtime.h>
#include <cuda_fp16.h>
#include <cstdint>
#include <math.h>

#define T_STEPS 512
#define BATCH   64
#define IN_DIM  1024
#define HID     1024
#define GATES   4096
#define NCTA    128

// ---------------- static scratch ----------------
__device__ uint32_t g_xfrag[(size_t)T_STEPS * 32768];   // 64 MB: x fp16, mma A-frag layout
__device__ uint32_t g_hfrag[(size_t)T_STEPS * 32768];   // 64 MB: h fp16, mma A-frag layout
__device__ int      g_flags[T_STEPS];

// ---------------- helpers ----------------
__device__ __forceinline__ uint32_t pack2h(__half a, __half b) {
    __half2 t = __halves2half2(a, b);
    return *reinterpret_cast<uint32_t*>(&t);
}
__device__ __forceinline__ void mma16816h(float* c, const uint32_t* a, const uint32_t* b) {
    asm volatile(
        "mma.sync.aligned.m16n8k16.row.col.f32.f16.f16.f32 "
        "{%0,%1,%2,%3}, {%4,%5,%6,%7}, {%8,%9}, {%0,%1,%2,%3};\n"
        : "+f"(c[0]), "+f"(c[1]), "+f"(c[2]), "+f"(c[3])
        : "r"(a[0]), "r"(a[1]), "r"(a[2]), "r"(a[3]), "r"(b[0]), "r"(b[1]));
}
__device__ __forceinline__ void flag_release_add(int* p) {
    asm volatile("red.release.gpu.global.add.s32 [%0], %1;" :: "l"(p), "r"(1) : "memory");
}
__device__ __forceinline__ int flag_acquire_ld(const int* p) {
    int v;
    asm volatile("ld.acquire.gpu.global.s32 %0, [%1];" : "=r"(v) : "l"(p) : "memory");
    return v;
}
#define BAR_SYNC(id, cnt)   asm volatile("bar.sync %0, %1;"   :: "r"(id), "r"(cnt) : "memory")
#define BAR_ARRIVE(id, cnt) asm volatile("bar.arrive %0, %1;" :: "r"(id), "r"(cnt) : "memory")
#define BFULL0  1
#define BEMPTY0 3
#define BREC    5

// =====================================================================
// Converter: x fp32 -> fp16 mma A-fragment layout.
// =====================================================================
__global__ __launch_bounds__(128)
void convert_x_kernel(const float* __restrict__ X)
{
    if (blockIdx.x == 0 && blockIdx.y == 0) {
        #pragma unroll
        for (int i = 0; i < 4; i++) g_flags[threadIdx.x + 128 * i] = 0;
    }
    const int kt = blockIdx.x;
    const int t  = blockIdx.y;
    const int mt = threadIdx.x >> 5;
    const int fl = threadIdx.x & 31;
    const int g  = fl >> 2;
    const int tg = fl & 3;
    const int bb = mt * 16 + g;
    const int k  = kt * 16 + tg * 2;

    const float* xt = X + (size_t)t * BATCH * IN_DIM;
    float2 r00 = *(const float2*)(xt + (size_t)bb * IN_DIM + k);
    float2 r10 = *(const float2*)(xt + (size_t)(bb + 8) * IN_DIM + k);
    float2 r01 = *(const float2*)(xt + (size_t)bb * IN_DIM + k + 8);
    float2 r11 = *(const float2*)(xt + (size_t)(bb + 8) * IN_DIM + k + 8);
    uint4 o;
    o.x = pack2h(__float2half(r00.x), __float2half(r00.y));
    o.y = pack2h(__float2half(r10.x), __float2half(r10.y));
    o.z = pack2h(__float2half(r01.x), __float2half(r01.y));
    o.w = pack2h(__float2half(r11.x), __float2half(r11.y));
    *(uint4*)(g_xfrag + (size_t)t * 32768 + kt * 512 + mt * 128 + fl * 4) = o;
}

// =====================================================================
// Fused persistent LSTM: 384 threads (R14 config).
//   warps 0-7  : recurrence (mt = w&3, nh = w>>2, full K) + early flag
//                poll + speculative H prefetch w/ reload fallback
//   warps 8-11 : xw producers (mh = pw&1, kh = pw>>1), B-frag reuse x2
// =====================================================================
#define WS_PITCH 520      // u32 per W column (520 % 32 == 8 -> conflict-free)
#define XWB_STRIDE 36     // floats per row
#define XWB_SIZE  (64 * XWB_STRIDE)

__global__ __launch_bounds__(384, 1)
void lstm_fused_kernel(const float* __restrict__ Wx,
                       const float* __restrict__ Wh,
                       const float* __restrict__ b,
                       float* __restrict__ out,
                       int write_tail)
{
    extern __shared__ char smraw[];
    uint32_t* Whs  = (uint32_t*)smraw;                  // 66560 B
    uint32_t* Wxs  = Whs + 32 * WS_PITCH;               // 66560 B
    float*    xwb  = (float*)(Wxs + 32 * WS_PITCH);     // 36864 B

    const int tid  = threadIdx.x;
    const int lane = tid & 31;
    const int warp = tid >> 5;
    const int g    = lane >> 2;
    const int tg   = lane & 3;
    const int j0   = blockIdx.x * 8;

    // ---- one-time: Wh & Wx slices -> SMEM fragment layout ----
    for (int i = tid; i < 32 * 1024; i += 384) {
        int c = i & 31;
        int k = i >> 5;
        int nhc = c >> 4, qc = (c >> 3) & 1, cc = c & 7;
        int gate = 2 * qc + (cc & 1);
        int jj   = nhc * 4 + (cc >> 1);
        size_t src = (size_t)k * GATES + gate * HID + j0 + jj;
        int kt = k >> 4, t4 = (k >> 1) & 3, w = (k >> 3) & 1, hf = k & 1;
        int word = c * WS_PITCH + kt * 8 + t4 * 2 + w;
        ((__half*)Whs)[word * 2 + hf] = __float2half(Wh[src]);
        ((__half*)Wxs)[word * 2 + hf] = __float2half(Wx[src]);
    }
    __syncthreads();

    if (warp < 8) {
        // ================== RECURRENCE WARPS ==================
        const int mt = warp & 3;
        const int nh = warp >> 2;
        const int wm = mt * 16;
        const int r0 = wm + g;
        const int r1 = wm + g + 8;
        const int j  = j0 + nh * 4 + tg;
        const int cc4 = (nh * 4 + tg) * 4;

        float breg[4] = { b[j], b[HID + j], b[2 * HID + j], b[3 * HID + j] };
        float creg[2] = {0.f, 0.f};

        for (int t = 0; t < T_STEPS; t++) {
            // ---- EARLY flag poll (overlaps the xw consume below) ----
            int fval = NCTA;
            if (t > 0 && lane == 0) fval = flag_acquire_ld(g_flags + (t - 1));

            // ---- consume xw[t] at top of step ----
            BAR_SYNC(BFULL0 + (t & 1), 384);
            const float* xb = xwb + (t & 1) * 2 * XWB_SIZE;
            float4 p00 = *(const float4*)(xb + r0 * XWB_STRIDE + cc4);
            float4 p01 = *(const float4*)(xb + XWB_SIZE + r0 * XWB_STRIDE + cc4);
            float4 p10 = *(const float4*)(xb + r1 * XWB_STRIDE + cc4);
            float4 p11 = *(const float4*)(xb + XWB_SIZE + r1 * XWB_STRIDE + cc4);
            BAR_ARRIVE(BEMPTY0 + (t & 1), 384);
            float4 x0 = make_float4(p00.x + p01.x + breg[0], p00.y + p01.y + breg[1],
                                    p00.z + p01.z + breg[2], p00.w + p01.w + breg[3]);
            float4 x1 = make_float4(p10.x + p11.x + breg[0], p10.y + p11.y + breg[1],
                                    p10.z + p11.z + breg[2], p10.w + p11.w + breg[3]);

            float acc[2][2][4];
            #pragma unroll
            for (int pp = 0; pp < 2; pp++)
                #pragma unroll
                for (int q = 0; q < 2; q++)
                    #pragma unroll
                    for (int c2 = 0; c2 < 4; c2++) acc[pp][q][c2] = 0.f;

            if (t > 0) {
                fval = __shfl_sync(0xffffffffu, fval, 0);
                const uint32_t* ab = g_hfrag + (size_t)(t - 1) * 32768
                                     + mt * 128 + lane * 4;

                // speculative H prefetch: if the early acquire saw NCTA, the
                // BFULL bar.sync above ordered it before these loads -> valid.
                uint4 H[8];
                #pragma unroll
                for (int q = 0; q < 8; q++) H[q] = *(const uint4*)(ab + q * 512);

                if (fval != NCTA) {
                    if (lane == 0) {
                        while (flag_acquire_ld(g_flags + (t - 1)) != NCTA) { }
                    }
                    __syncwarp();
                    #pragma unroll
                    for (int q = 0; q < 8; q++) H[q] = *(const uint4*)(ab + q * 512);
                }

                #pragma unroll 8
                for (int kt = 0; kt < 64; kt++) {
                    int s = kt & 7;
                    uint32_t ah[4] = {H[s].x, H[s].y, H[s].z, H[s].w};
                    float* a0 = acc[kt & 1][0];
                    float* a1 = acc[kt & 1][1];
                    {
                        int c = nh * 16 + g;
                        uint2 bf = *(const uint2*)(Whs + c * WS_PITCH + kt * 8 + tg * 2);
                        uint32_t bh[2] = {bf.x, bf.y};
                        mma16816h(a0, ah, bh);
                    }
                    {
                        int c = nh * 16 + 8 + g;
                        uint2 bf = *(const uint2*)(Whs + c * WS_PITCH + kt * 8 + tg * 2);
                        uint32_t bh[2] = {bf.x, bf.y};
                        mma16816h(a1, ah, bh);
                    }
                    if (kt + 8 < 64) H[s] = *(const uint4*)(ab + (kt + 8) * 512);
                }
            }

            // ---- in-register activations ----
            float hn[2], cn[2];
            #pragma unroll
            for (int rr = 0; rr < 2; rr++) {
                float xi = rr ? x1.x : x0.x;
                float xf = rr ? x1.y : x0.y;
                float xG = rr ? x1.z : x0.z;
                float xo = rr ? x1.w : x0.w;
                float gi = acc[0][0][2 * rr + 0] + acc[1][0][2 * rr + 0] + xi;
                float gf = acc[0][0][2 * rr + 1] + acc[1][0][2 * rr + 1] + xf;
                float gg = acc[0][1][2 * rr + 0] + acc[1][1][2 * rr + 0] + xG;
                float go = acc[0][1][2 * rr + 1] + acc[1][1][2 * rr + 1] + xo;
                float iv = 1.f / (1.f + expf(-gi));
                float fv = 1.f / (1.f + expf(-gf));
                float gv = tanhf(gg);
                float ov = 1.f / (1.f + expf(-go));
                float c_ = fv * creg[rr] + iv * gv;
                float h_ = ov * tanhf(c_);
                creg[rr] = c_;
                cn[rr] = c_; hn[rr] = h_;
            }

            // ---- publish h fragments ----
            {
                uint32_t packed = pack2h(__float2half(hn[0]), __float2half(hn[1]));
                uint32_t nb = __shfl_xor_sync(0xffffffffu, packed, 1);
                if ((tg & 1) == 0) {
                    uint32_t f0 = (packed & 0xffffu) | (nb << 16);       // row r0
                    uint32_t f1 = (packed >> 16) | (nb & 0xffff0000u);   // row r1
                    int kk = j & 15, kt = j >> 4;
                    int fl = g * 4 + ((kk >> 1) & 3);
                    int rg0 = (kk >> 3) << 1;
                    size_t fb = (size_t)t * 32768 + (size_t)kt * 512 + mt * 128 + fl * 4 + rg0;
                    *(uint2*)(g_hfrag + fb) = make_uint2(f0, f1);
                }
            }

            BAR_SYNC(BREC, 256);
            if (tid == 0) flag_release_add(g_flags + t);

            // ---- off-critical-path output stores ----
            float* hdst = out + (size_t)t * BATCH * HID;
            hdst[(size_t)r0 * HID + j] = hn[0];
            hdst[(size_t)r1 * HID + j] = hn[1];
            if (t == T_STEPS - 1 && write_tail) {
                size_t base = (size_t)T_STEPS * BATCH * HID;
                out[base + (size_t)r0 * HID + j] = hn[0];
                out[base + (size_t)r1 * HID + j] = hn[1];
                out[base + BATCH * HID + (size_t)r0 * HID + j] = cn[0];
                out[base + BATCH * HID + (size_t)r1 * HID + j] = cn[1];
            }
        }
    } else {
        // ================== XW PRODUCER WARPS ==================
        const int pw = warp - 8;
        const int mh = pw & 1;
        const int kh = pw >> 1;

        for (int t = 0; t < T_STEPS; t++) {
            if (t >= 2) BAR_SYNC(BEMPTY0 + (t & 1), 384);

            const uint32_t* abA = g_xfrag + (size_t)t * 32768
                                  + (size_t)(kh * 32) * 512 + (2 * mh) * 128 + lane * 4;
            const uint32_t* abB = abA + 128;

            uint4 HA[4], HB[4];
            #pragma unroll
            for (int q = 0; q < 4; q++) {
                HA[q] = *(const uint4*)(abA + q * 512);
                HB[q] = *(const uint4*)(abB + q * 512);
            }

            float acc[2][4][4];
            #pragma unroll
            for (int m2 = 0; m2 < 2; m2++)
                #pragma unroll
                for (int q = 0; q < 4; q++)
                    #pragma unroll
                    for (int c2 = 0; c2 < 4; c2++) acc[m2][q][c2] = 0.f;

            #pragma unroll 4
            for (int kt2 = 0; kt2 < 32; kt2++) {
                int s = kt2 & 3;
                int ktg = kh * 32 + kt2;
                uint32_t ahA[4] = {HA[s].x, HA[s].y, HA[s].z, HA[s].w};
                uint32_t ahB[4] = {HB[s].x, HB[s].y, HB[s].z, HB[s].w};
                #pragma unroll
                for (int ct = 0; ct < 4; ct++) {
                    uint2 bf = *(const uint2*)(Wxs + (ct * 8 + g) * WS_PITCH + ktg * 8 + tg * 2);
                    uint32_t bh[2] = {bf.x, bf.y};
                    mma16816h(acc[0][ct], ahA, bh);
                    mma16816h(acc[1][ct], ahB, bh);
                }
                if (kt2 + 4 < 32) {
                    HA[s] = *(const uint4*)(abA + (kt2 + 4) * 512);
                    HB[s] = *(const uint4*)(abB + (kt2 + 4) * 512);
                }
            }

            float* xb = xwb + ((t & 1) * 2 + kh) * XWB_SIZE;
            #pragma unroll
            for (int m2 = 0; m2 < 2; m2++) {
                int rb = mh * 32 + m2 * 16 + g;
                #pragma unroll
                for (int nh2 = 0; nh2 < 2; nh2++) {
                    int col4 = (nh2 * 4 + tg) * 4;
                    float4 v0 = make_float4(acc[m2][nh2 * 2][0], acc[m2][nh2 * 2][1],
                                            acc[m2][nh2 * 2 + 1][0], acc[m2][nh2 * 2 + 1][1]);
                    float4 v1 = make_float4(acc[m2][nh2 * 2][2], acc[m2][nh2 * 2][3],
                                            acc[m2][nh2 * 2 + 1][2], acc[m2][nh2 * 2 + 1][3]);
                    *(float4*)(xb + rb * XWB_STRIDE + col4)       = v0;
                    *(float4*)(xb + (rb + 8) * XWB_STRIDE + col4) = v1;
                }
            }
            BAR_ARRIVE(BFULL0 + (t & 1), 384);
        }
    }
}

// =====================================================================
extern "C" void kernel_launch(void* const* d_in, const int* in_sizes, int n_in,
                              void* d_out, int out_size)
{
    const float* x  = (const float*)d_in[0];   // [512,64,1024]
    const float* Wx = (const float*)d_in[1];   // [1024,4096]
    const float* Wh = (const float*)d_in[2];   // [1024,4096]
    const float* b  = (const float*)d_in[3];   // [4096]
    float* out = (float*)d_out;

    convert_x_kernel<<<dim3(64, T_STEPS), 128>>>(x);

    const int smemB = 2 * (32 * WS_PITCH * 4) + 4 * XWB_SIZE * 4;  // 133120 + 36864
    cudaFuncSetAttribute(lstm_fused_kernel,
                         cudaFuncAttributeMaxDynamicSharedMemorySize, smemB);
    int write_tail = (out_size > T_STEPS * BATCH * HID) ? 1 : 0;
    lstm_fused_kernel<<<NCTA, 384, smemB>>>(Wx, Wh, b, out, write_tail);
}